// round 16
// baseline (speedup 1.0000x reference)
#include <cuda_runtime.h>
#include <cuda_bf16.h>

// OHEM loss, C=1 specialization (FINAL — converged; 3x repeat-benched):
//   ce == 0 exactly (logsumexp over singleton axis minus the gathered element),
//   so cls_loss == 0 and the hard-negative mining is dead code.
//   out = 0.2 * sum_{pos}(smoothL1(loc_preds - loc_targets)) / num_pos
//
// Measured invariants (15 rounds): traffic floor ~209 MB (128B line
// granularity; predication saves only the 6% all-negative lines); streaming
// plateau ~5.7 TB/s / ~72% DRAM busy regardless of MLP depth, load width,
// cache hints, or schedule; occupancy at the 64-warp/SM cap. Best shape:
// one-wave grid-stride (uniform L2/HBM channel load), 4-way front-batched ct,
// predicated __ldcs float4 bodies, in-kernel ticket finalize.
// ~36-37 us end-to-end, rel_err 0.

#define NBLOCKS  1184   // 148 SMs * 8 blocks -> exactly one wave
#define NTHREADS 256
#define NWARPS   (NTHREADS / 32)

__device__ float g_partial_sum[NBLOCKS];
__device__ int   g_partial_cnt[NBLOCKS];
__device__ int   g_ticket = 0;          // self-resets each run; deterministic

__device__ __forceinline__ float smooth_l1(float d) {
    float ax = fabsf(d);
    return (ax < 1.0f) ? 0.5f * d * d : ax - 0.5f;
}

__device__ __forceinline__ float anchor_loss_cs(const float4* __restrict__ lp,
                                                const float4* __restrict__ lt,
                                                int i) {
    // Evict-first streaming loads: data is read exactly once.
    float4 p0 = __ldcs(lp + 2 * i);
    float4 p1 = __ldcs(lp + 2 * i + 1);
    float4 t0 = __ldcs(lt + 2 * i);
    float4 t1 = __ldcs(lt + 2 * i + 1);
    float s = smooth_l1(p0.x - t0.x);
    s += smooth_l1(p0.y - t0.y);
    s += smooth_l1(p0.z - t0.z);
    s += smooth_l1(p0.w - t0.w);
    s += smooth_l1(p1.x - t1.x);
    s += smooth_l1(p1.y - t1.y);
    s += smooth_l1(p1.z - t1.z);
    s += smooth_l1(p1.w - t1.w);
    return s;
}

__global__ __launch_bounds__(NTHREADS, 8)
void ohem_fused_kernel(const float4* __restrict__ lp,   // loc_preds  (2 float4/anchor)
                       const float4* __restrict__ lt,   // loc_targets
                       const int*    __restrict__ ct,   // cls_targets
                       int nAnchors,
                       float* __restrict__ out)
{
    float sum = 0.0f;
    int   cnt = 0;

    const int stride  = gridDim.x * blockDim.x;
    const int stride4 = 4 * stride;
    int i = blockIdx.x * blockDim.x + threadIdx.x;

    // 4-way unrolled: all four ct loads issued before any body executes.
    for (; i + 3 * stride < nAnchors; i += stride4) {
        int ta = __ldcs(ct + i);
        int tb = __ldcs(ct + i + stride);
        int tc = __ldcs(ct + i + 2 * stride);
        int td = __ldcs(ct + i + 3 * stride);
        if (ta > 0) { sum += anchor_loss_cs(lp, lt, i);              cnt++; }
        if (tb > 0) { sum += anchor_loss_cs(lp, lt, i + stride);     cnt++; }
        if (tc > 0) { sum += anchor_loss_cs(lp, lt, i + 2 * stride); cnt++; }
        if (td > 0) { sum += anchor_loss_cs(lp, lt, i + 3 * stride); cnt++; }
    }
    for (; i < nAnchors; i += stride) {
        int t = __ldcs(ct + i);
        if (t > 0) { sum += anchor_loss_cs(lp, lt, i); cnt++; }
    }

    // intra-block tree reduction
    #pragma unroll
    for (int off = 16; off > 0; off >>= 1) {
        sum += __shfl_xor_sync(0xFFFFFFFFu, sum, off);
        cnt += __shfl_xor_sync(0xFFFFFFFFu, cnt, off);
    }

    __shared__ float ssum[NWARPS];
    __shared__ int   scnt[NWARPS];
    __shared__ bool  s_last;
    int lane = threadIdx.x & 31;
    int wid  = threadIdx.x >> 5;
    if (lane == 0) { ssum[wid] = sum; scnt[wid] = cnt; }
    __syncthreads();

    if (wid == 0) {
        float s = (lane < NWARPS) ? ssum[lane] : 0.0f;
        int   c = (lane < NWARPS) ? scnt[lane] : 0;
        #pragma unroll
        for (int off = 16; off > 0; off >>= 1) {
            s += __shfl_xor_sync(0xFFFFFFFFu, s, off);
            c += __shfl_xor_sync(0xFFFFFFFFu, c, off);
        }
        if (lane == 0) {
            g_partial_sum[blockIdx.x] = s;
            g_partial_cnt[blockIdx.x] = c;
            __threadfence();
            int ticket = atomicAdd(&g_ticket, 1);
            s_last = (ticket == gridDim.x - 1);
        }
    }
    __syncthreads();

    // last-arriving block folds all partials (fixed tree order: deterministic)
    if (s_last) {
        float fs = 0.0f;
        int   fc = 0;
        for (int k = threadIdx.x; k < NBLOCKS; k += NTHREADS) {
            fs += ((volatile float*)g_partial_sum)[k];
            fc += ((volatile int*)g_partial_cnt)[k];
        }
        #pragma unroll
        for (int off = 16; off > 0; off >>= 1) {
            fs += __shfl_xor_sync(0xFFFFFFFFu, fs, off);
            fc += __shfl_xor_sync(0xFFFFFFFFu, fc, off);
        }
        if (lane == 0) { ssum[wid] = fs; scnt[wid] = fc; }
        __syncthreads();
        if (wid == 0) {
            float s2 = (lane < NWARPS) ? ssum[lane] : 0.0f;
            int   c2 = (lane < NWARPS) ? scnt[lane] : 0;
            #pragma unroll
            for (int off = 16; off > 0; off >>= 1) {
                s2 += __shfl_xor_sync(0xFFFFFFFFu, s2, off);
                c2 += __shfl_xor_sync(0xFFFFFFFFu, c2, off);
            }
            if (lane == 0) {
                out[0] = 0.2f * s2 / (float)c2;   // cls term exactly 0 for C=1
                g_ticket = 0;                     // reset for next graph replay
            }
        }
    }
}

extern "C" void kernel_launch(void* const* d_in, const int* in_sizes, int n_in,
                              void* d_out, int out_size)
{
    // inputs: loc_preds [B,A,8] f32, loc_targets [B,A,8] f32,
    //         cls_preds [B,A,1] f32 (UNUSED), cls_targets [B,A] i32
    const float4* lp = (const float4*)d_in[0];
    const float4* lt = (const float4*)d_in[1];
    const int*    ct = (const int*)d_in[3];
    float* out = (float*)d_out;

    int nAnchors = in_sizes[3];      // 3,200,000

    ohem_fused_kernel<<<NBLOCKS, NTHREADS>>>(lp, lt, ct, nAnchors, out);
}

// round 17
// speedup vs baseline: 1.0068x; 1.0068x over previous
#include <cuda_runtime.h>
#include <cuda_bf16.h>

// OHEM loss, C=1 specialization (FINAL — converged; 4x repeat-benched at
// 36.9-37.6 us, rel_err 0.0):
//   ce == 0 exactly (logsumexp over singleton axis minus the gathered element),
//   so cls_loss == 0 and the hard-negative mining is dead code.
//   out = 0.2 * sum_{pos}(smoothL1(loc_preds - loc_targets)) / num_pos
//
// Measured invariants (16 rounds, 14 builds): traffic floor ~209 MB (128B
// line granularity; predication saves only the 6% all-negative lines);
// streaming plateau ~5.7 TB/s / ~72% DRAM busy regardless of MLP depth,
// load width, cache hints, or schedule; occupancy at the 64-warp/SM cap.
// Best shape: one-wave grid-stride (uniform L2/HBM channel load), 4-way
// front-batched ct, predicated __ldcs float4 bodies, in-kernel ticket
// finalize.

#define NBLOCKS  1184   // 148 SMs * 8 blocks -> exactly one wave
#define NTHREADS 256
#define NWARPS   (NTHREADS / 32)

__device__ float g_partial_sum[NBLOCKS];
__device__ int   g_partial_cnt[NBLOCKS];
__device__ int   g_ticket = 0;          // self-resets each run; deterministic

__device__ __forceinline__ float smooth_l1(float d) {
    float ax = fabsf(d);
    return (ax < 1.0f) ? 0.5f * d * d : ax - 0.5f;
}

__device__ __forceinline__ float anchor_loss_cs(const float4* __restrict__ lp,
                                                const float4* __restrict__ lt,
                                                int i) {
    // Evict-first streaming loads: data is read exactly once.
    float4 p0 = __ldcs(lp + 2 * i);
    float4 p1 = __ldcs(lp + 2 * i + 1);
    float4 t0 = __ldcs(lt + 2 * i);
    float4 t1 = __ldcs(lt + 2 * i + 1);
    float s = smooth_l1(p0.x - t0.x);
    s += smooth_l1(p0.y - t0.y);
    s += smooth_l1(p0.z - t0.z);
    s += smooth_l1(p0.w - t0.w);
    s += smooth_l1(p1.x - t1.x);
    s += smooth_l1(p1.y - t1.y);
    s += smooth_l1(p1.z - t1.z);
    s += smooth_l1(p1.w - t1.w);
    return s;
}

__global__ __launch_bounds__(NTHREADS, 8)
void ohem_fused_kernel(const float4* __restrict__ lp,   // loc_preds  (2 float4/anchor)
                       const float4* __restrict__ lt,   // loc_targets
                       const int*    __restrict__ ct,   // cls_targets
                       int nAnchors,
                       float* __restrict__ out)
{
    float sum = 0.0f;
    int   cnt = 0;

    const int stride  = gridDim.x * blockDim.x;
    const int stride4 = 4 * stride;
    int i = blockIdx.x * blockDim.x + threadIdx.x;

    // 4-way unrolled: all four ct loads issued before any body executes.
    for (; i + 3 * stride < nAnchors; i += stride4) {
        int ta = __ldcs(ct + i);
        int tb = __ldcs(ct + i + stride);
        int tc = __ldcs(ct + i + 2 * stride);
        int td = __ldcs(ct + i + 3 * stride);
        if (ta > 0) { sum += anchor_loss_cs(lp, lt, i);              cnt++; }
        if (tb > 0) { sum += anchor_loss_cs(lp, lt, i + stride);     cnt++; }
        if (tc > 0) { sum += anchor_loss_cs(lp, lt, i + 2 * stride); cnt++; }
        if (td > 0) { sum += anchor_loss_cs(lp, lt, i + 3 * stride); cnt++; }
    }
    for (; i < nAnchors; i += stride) {
        int t = __ldcs(ct + i);
        if (t > 0) { sum += anchor_loss_cs(lp, lt, i); cnt++; }
    }

    // intra-block tree reduction
    #pragma unroll
    for (int off = 16; off > 0; off >>= 1) {
        sum += __shfl_xor_sync(0xFFFFFFFFu, sum, off);
        cnt += __shfl_xor_sync(0xFFFFFFFFu, cnt, off);
    }

    __shared__ float ssum[NWARPS];
    __shared__ int   scnt[NWARPS];
    __shared__ bool  s_last;
    int lane = threadIdx.x & 31;
    int wid  = threadIdx.x >> 5;
    if (lane == 0) { ssum[wid] = sum; scnt[wid] = cnt; }
    __syncthreads();

    if (wid == 0) {
        float s = (lane < NWARPS) ? ssum[lane] : 0.0f;
        int   c = (lane < NWARPS) ? scnt[lane] : 0;
        #pragma unroll
        for (int off = 16; off > 0; off >>= 1) {
            s += __shfl_xor_sync(0xFFFFFFFFu, s, off);
            c += __shfl_xor_sync(0xFFFFFFFFu, c, off);
        }
        if (lane == 0) {
            g_partial_sum[blockIdx.x] = s;
            g_partial_cnt[blockIdx.x] = c;
            __threadfence();
            int ticket = atomicAdd(&g_ticket, 1);
            s_last = (ticket == gridDim.x - 1);
        }
    }
    __syncthreads();

    // last-arriving block folds all partials (fixed tree order: deterministic)
    if (s_last) {
        float fs = 0.0f;
        int   fc = 0;
        for (int k = threadIdx.x; k < NBLOCKS; k += NTHREADS) {
            fs += ((volatile float*)g_partial_sum)[k];
            fc += ((volatile int*)g_partial_cnt)[k];
        }
        #pragma unroll
        for (int off = 16; off > 0; off >>= 1) {
            fs += __shfl_xor_sync(0xFFFFFFFFu, fs, off);
            fc += __shfl_xor_sync(0xFFFFFFFFu, fc, off);
        }
        if (lane == 0) { ssum[wid] = fs; scnt[wid] = fc; }
        __syncthreads();
        if (wid == 0) {
            float s2 = (lane < NWARPS) ? ssum[lane] : 0.0f;
            int   c2 = (lane < NWARPS) ? scnt[lane] : 0;
            #pragma unroll
            for (int off = 16; off > 0; off >>= 1) {
                s2 += __shfl_xor_sync(0xFFFFFFFFu, s2, off);
                c2 += __shfl_xor_sync(0xFFFFFFFFu, c2, off);
            }
            if (lane == 0) {
                out[0] = 0.2f * s2 / (float)c2;   // cls term exactly 0 for C=1
                g_ticket = 0;                     // reset for next graph replay
            }
        }
    }
}

extern "C" void kernel_launch(void* const* d_in, const int* in_sizes, int n_in,
                              void* d_out, int out_size)
{
    // inputs: loc_preds [B,A,8] f32, loc_targets [B,A,8] f32,
    //         cls_preds [B,A,1] f32 (UNUSED), cls_targets [B,A] i32
    const float4* lp = (const float4*)d_in[0];
    const float4* lt = (const float4*)d_in[1];
    const int*    ct = (const int*)d_in[3];
    float* out = (float*)d_out;

    int nAnchors = in_sizes[3];      // 3,200,000

    ohem_fused_kernel<<<NBLOCKS, NTHREADS>>>(lp, lt, ct, nAnchors, out);
}